// round 5
// baseline (speedup 1.0000x reference)
#include <cuda_runtime.h>
#include <cuda_bf16.h>
#include <cstdint>

#define N_NODES 50000
#define N_EDGES 800000
#define HID 64
#define CAT_DIM 256
#define CSR_MAX (N_EDGES + 7 * N_NODES + 16)   // padded CSR capacity

typedef unsigned long long ull;

// ------------------------- device scratch (static, alloc-free) ----------------
__device__ int   g_cnt_in_i[N_NODES];
__device__ int   g_cnt_out_i[N_NODES];
__device__ float g_dout_is[N_NODES];
__device__ float g_din_is[N_NODES];
__device__ int   g_row_ptr[N_NODES + 1];
__device__ int   g_cursor[N_NODES];
__device__ __align__(16) int g_csr_src[CSR_MAX];
__device__ float g_y[(size_t)(N_NODES + 1) * HID];   // +1 zero row for CSR padding
__device__ float g_cat[(size_t)N_NODES * CAT_DIM];   // JK concat buffer [N,256]

// ------------------------- helpers --------------------------------------------
__device__ __forceinline__ ull pack2(float a) {
    ull r; asm("mov.b64 %0, {%1, %1};" : "=l"(r) : "f"(a)); return r;
}
__device__ __forceinline__ void ffma2(ull& d, ull a, ull b) {
    asm("fma.rn.f32x2 %0, %1, %2, %0;" : "+l"(d) : "l"(a), "l"(b));
}
__device__ __forceinline__ float lo32(ull v) { return __uint_as_float((unsigned)v); }
__device__ __forceinline__ float hi32(ull v) { return __uint_as_float((unsigned)(v >> 32)); }

// ------------------------- CSR build ------------------------------------------
__global__ void k_zero_deg() {
    int i = blockIdx.x * blockDim.x + threadIdx.x;
    if (i < N_NODES) { g_cnt_in_i[i] = 0; g_cnt_out_i[i] = 0; }
}

// prefill CSR with the zero-row index and zero the pad row of g_y
__global__ void k_prefill() {
    int i = blockIdx.x * blockDim.x + threadIdx.x;
    int4* p = (int4*)g_csr_src;
    if (i < CSR_MAX / 4)
        p[i] = make_int4(N_NODES, N_NODES, N_NODES, N_NODES);
    if (i < HID / 4)
        *(float4*)(g_y + (size_t)N_NODES * HID + i * 4) = make_float4(0.f, 0.f, 0.f, 0.f);
}

__global__ void k_deg_count(const int* __restrict__ src, const int* __restrict__ dst) {
    int e = blockIdx.x * blockDim.x + threadIdx.x;
    if (e < N_EDGES) {
        atomicAdd(&g_cnt_in_i[dst[e]], 1);
        atomicAdd(&g_cnt_out_i[src[e]], 1);
    }
}

// single block, 1024 threads: exclusive scan of padded in-degrees -> row_ptr,
// plus rsqrt finalization of both degree vectors.
__global__ __launch_bounds__(1024) void k_scan_build() {
    __shared__ int sums[1024];
    const int t  = threadIdx.x;
    const int CH = (N_NODES + 1023) / 1024;
    const int beg = t * CH;
    const int end = min(beg + CH, N_NODES);

    int s = 0;
    for (int i = beg; i < end; ++i) s += (g_cnt_in_i[i] + 7) & ~7;
    sums[t] = s;
    __syncthreads();

    for (int off = 1; off < 1024; off <<= 1) {
        int add = (t >= off) ? sums[t - off] : 0;
        __syncthreads();
        sums[t] += add;
        __syncthreads();
    }

    int running = sums[t] - s;   // exclusive prefix (padded)
    for (int i = beg; i < end; ++i) {
        int c = g_cnt_in_i[i];
        g_row_ptr[i] = running;
        g_cursor[i]  = running;
        running += (c + 7) & ~7;
        g_din_is[i]  = rsqrtf((float)max(c, 1));
        g_dout_is[i] = rsqrtf((float)max(g_cnt_out_i[i], 1));
    }
    if (end == N_NODES) g_row_ptr[N_NODES] = running;
}

__global__ void k_csr_fill(const int* __restrict__ src, const int* __restrict__ dst) {
    int e = blockIdx.x * blockDim.x + threadIdx.x;
    if (e < N_EDGES) {
        int pos = atomicAdd(&g_cursor[dst[e]], 1);
        g_csr_src[pos] = src[e];
    }
}

// ------------------------- FFMA2 GEMM: Y[n,64] = (diag(s?) X[n,K]) @ W[K,64] ----
template<int K, bool SCALE>
__global__ __launch_bounds__(256)
void k_gemm(const float* __restrict__ X, int ldx,
            const float* __restrict__ W,
            float* __restrict__ Y, int n)
{
    __shared__ float Xs[32][132];
    __shared__ ull   Wd[32][64];

    const int tid  = threadIdx.x;
    const int row0 = blockIdx.x * 128;
    const int r0   = (tid >> 4) * 8;
    const int c0   = (tid & 15) * 4;

    ull acc[4][4];
    #pragma unroll
    for (int p = 0; p < 4; ++p)
        #pragma unroll
        for (int j = 0; j < 4; ++j) acc[p][j] = 0ull;

    for (int kk = 0; kk < K; kk += 32) {
        #pragma unroll
        for (int j = 0; j < 4; ++j) {
            int idx = tid + j * 256;
            int r   = idx >> 3;
            int c4  = (idx & 7) * 4;
            int row = row0 + r;
            float4 v = make_float4(0.f, 0.f, 0.f, 0.f);
            if (row < n) {
                v = *(const float4*)(X + (size_t)row * ldx + kk + c4);
                if (SCALE) {
                    float s = __ldg(&g_dout_is[row]);
                    v.x *= s; v.y *= s; v.z *= s; v.w *= s;
                }
            }
            Xs[c4 + 0][r] = v.x;
            Xs[c4 + 1][r] = v.y;
            Xs[c4 + 2][r] = v.z;
            Xs[c4 + 3][r] = v.w;
        }
        #pragma unroll
        for (int j = 0; j < 8; ++j) {
            int idx = tid + j * 256;
            int k   = idx >> 6;
            int c   = idx & 63;
            Wd[k][c] = pack2(W[(size_t)(kk + k) * 64 + c]);
        }
        __syncthreads();

        #pragma unroll
        for (int k = 0; k < 32; ++k) {
            double2 xa = *(const double2*)&Xs[k][r0];
            double2 xb = *(const double2*)&Xs[k][r0 + 4];
            double2 wA = *(const double2*)&Wd[k][c0];
            double2 wB = *(const double2*)&Wd[k][c0 + 2];
            ull a0 = __double_as_longlong(xa.x);
            ull a1 = __double_as_longlong(xa.y);
            ull a2 = __double_as_longlong(xb.x);
            ull a3 = __double_as_longlong(xb.y);
            ull w0 = __double_as_longlong(wA.x);
            ull w1 = __double_as_longlong(wA.y);
            ull w2 = __double_as_longlong(wB.x);
            ull w3 = __double_as_longlong(wB.y);
            ffma2(acc[0][0], a0, w0); ffma2(acc[0][1], a0, w1); ffma2(acc[0][2], a0, w2); ffma2(acc[0][3], a0, w3);
            ffma2(acc[1][0], a1, w0); ffma2(acc[1][1], a1, w1); ffma2(acc[1][2], a1, w2); ffma2(acc[1][3], a1, w3);
            ffma2(acc[2][0], a2, w0); ffma2(acc[2][1], a2, w1); ffma2(acc[2][2], a2, w2); ffma2(acc[2][3], a2, w3);
            ffma2(acc[3][0], a3, w0); ffma2(acc[3][1], a3, w1); ffma2(acc[3][2], a3, w2); ffma2(acc[3][3], a3, w3);
        }
        __syncthreads();
    }

    #pragma unroll
    for (int p = 0; p < 4; ++p) {
        int rowA = row0 + r0 + 2 * p;
        if (rowA < n) {
            float4 o = make_float4(lo32(acc[p][0]), lo32(acc[p][1]), lo32(acc[p][2]), lo32(acc[p][3]));
            *(float4*)(Y + (size_t)rowA * 64 + c0) = o;
        }
        if (rowA + 1 < n) {
            float4 o = make_float4(hi32(acc[p][0]), hi32(acc[p][1]), hi32(acc[p][2]), hi32(acc[p][3]));
            *(float4*)(Y + (size_t)(rowA + 1) * 64 + c0) = o;
        }
    }
}

// ------------------------- pull aggregation (MLP=8) -----------------------------
// out[node] = post( sum over padded CSR row of g_y[csr_src[i]] ), pad -> zero row.
// 16 threads per node, float4 per thread; 8 edges per iteration, all loads
// independent (2x int4 index loads + 8 row gathers in flight).
template<bool RELU>
__global__ __launch_bounds__(256)
void k_pull(const float* __restrict__ bias, float* __restrict__ outp, int ldo)
{
    int t = blockIdx.x * blockDim.x + threadIdx.x;
    int node = t >> 4;
    if (node >= N_NODES) return;
    int lane4 = (t & 15) << 2;

    int beg = __ldg(&g_row_ptr[node]);
    int end = __ldg(&g_row_ptr[node + 1]);

    float4 accA = make_float4(0.f, 0.f, 0.f, 0.f);
    float4 accB = make_float4(0.f, 0.f, 0.f, 0.f);

    for (int i = beg; i < end; i += 8) {
        int4 sA = __ldg((const int4*)&g_csr_src[i]);
        int4 sB = __ldg((const int4*)&g_csr_src[i + 4]);
        const float* base = g_y + lane4;
        float4 v0 = *(const float4*)(base + (size_t)sA.x * HID);
        float4 v1 = *(const float4*)(base + (size_t)sA.y * HID);
        float4 v2 = *(const float4*)(base + (size_t)sA.z * HID);
        float4 v3 = *(const float4*)(base + (size_t)sA.w * HID);
        float4 v4 = *(const float4*)(base + (size_t)sB.x * HID);
        float4 v5 = *(const float4*)(base + (size_t)sB.y * HID);
        float4 v6 = *(const float4*)(base + (size_t)sB.z * HID);
        float4 v7 = *(const float4*)(base + (size_t)sB.w * HID);
        accA.x += (v0.x + v1.x) + (v2.x + v3.x);
        accA.y += (v0.y + v1.y) + (v2.y + v3.y);
        accA.z += (v0.z + v1.z) + (v2.z + v3.z);
        accA.w += (v0.w + v1.w) + (v2.w + v3.w);
        accB.x += (v4.x + v5.x) + (v6.x + v7.x);
        accB.y += (v4.y + v5.y) + (v6.y + v7.y);
        accB.z += (v4.z + v5.z) + (v6.z + v7.z);
        accB.w += (v4.w + v5.w) + (v6.w + v7.w);
    }

    float4 acc = make_float4(accA.x + accB.x, accA.y + accB.y,
                             accA.z + accB.z, accA.w + accB.w);
    float4 bv = *(const float4*)(bias + lane4);
    float4 o;
    if (RELU) {
        float sc = __ldg(&g_din_is[node]);
        o.x = fmaxf(fmaf(acc.x, sc, bv.x), 0.f);
        o.y = fmaxf(fmaf(acc.y, sc, bv.y), 0.f);
        o.z = fmaxf(fmaf(acc.z, sc, bv.z), 0.f);
        o.w = fmaxf(fmaf(acc.w, sc, bv.w), 0.f);
    } else {
        o.x = acc.x + bv.x; o.y = acc.y + bv.y;
        o.z = acc.z + bv.z; o.w = acc.w + bv.w;
    }
    *(float4*)(outp + (size_t)node * ldo + lane4) = o;
}

// ------------------------- launch ----------------------------------------------
extern "C" void kernel_launch(void* const* d_in, const int* in_sizes, int n_in,
                              void* d_out, int out_size)
{
    const float* feat  = (const float*)d_in[0];
    const int*   src   = (const int*)d_in[1];
    const int*   dst   = (const int*)d_in[2];
    const float* W[4]  = { (const float*)d_in[3], (const float*)d_in[5],
                           (const float*)d_in[7], (const float*)d_in[9] };
    const float* B[4]  = { (const float*)d_in[4], (const float*)d_in[6],
                           (const float*)d_in[8], (const float*)d_in[10] };
    const float* W_mlp = (const float*)d_in[11];
    const float* b_mlp = (const float*)d_in[12];
    float* out = (float*)d_out;

    float *cat_p = nullptr, *y_p = nullptr;
    cudaGetSymbolAddress((void**)&cat_p, g_cat);
    cudaGetSymbolAddress((void**)&y_p, g_y);

    const int T = 256;
    const int gN    = (N_NODES + T - 1) / T;
    const int gE    = (N_EDGES + T - 1) / T;
    const int gPre  = (CSR_MAX / 4 + T - 1) / T;
    const int gPull = (N_NODES * 16 + T - 1) / T;
    const int gGemm = (N_NODES + 127) / 128;

    // CSR build + degree normalizers
    k_zero_deg<<<gN, T>>>();
    k_prefill<<<gPre, T>>>();
    k_deg_count<<<gE, T>>>(src, dst);
    k_scan_build<<<1, 1024>>>();
    k_csr_fill<<<gE, T>>>(src, dst);

    // layer 0: K = 256, input = feat
    k_gemm<256, true><<<gGemm, T>>>(feat, 256, W[0], y_p, N_NODES);
    k_pull<true><<<gPull, T>>>(B[0], cat_p + 0 * HID, CAT_DIM);

    // layers 1..3: K = 64, input = cat column block of previous layer
    for (int l = 1; l < 4; ++l) {
        k_gemm<64, true><<<gGemm, T>>>(cat_p + (l - 1) * HID, CAT_DIM, W[l], y_p, N_NODES);
        k_pull<true><<<gPull, T>>>(B[l], cat_p + l * HID, CAT_DIM);
    }

    // final: out = segment_sum((cat @ W_mlp)[src]) + b  (linearity reorder)
    k_gemm<256, false><<<gGemm, T>>>(cat_p, CAT_DIM, W_mlp, y_p, N_NODES);
    k_pull<false><<<gPull, T>>>(b_mlp, out, HID);
}

// round 7
// speedup vs baseline: 1.4440x; 1.4440x over previous
#include <cuda_runtime.h>
#include <cuda_bf16.h>
#include <cstdint>

#define N_NODES 50000
#define N_EDGES 800000
#define HID 64
#define CAT_DIM 256
#define CSR_MAX (N_EDGES + 7 * N_NODES + 16)   // padded CSR capacity
#define SCAN_BLOCKS 196                        // 196*256 = 50176 >= N_NODES

typedef unsigned long long ull;

// ------------------------- device scratch (static, alloc-free) ----------------
__device__ int   g_cnt_in_i[N_NODES];
__device__ int   g_cnt_out_i[N_NODES];
__device__ float g_dout_is[N_NODES];
__device__ float g_din_is[N_NODES];
__device__ int   g_row_ptr[N_NODES + 1];
__device__ int   g_cursor[N_NODES];
__device__ int   g_blk_sums[SCAN_BLOCKS];
__device__ int   g_blk_off[SCAN_BLOCKS];
__device__ __align__(16) int g_csr_src[CSR_MAX];
__device__ float g_y[(size_t)(N_NODES + 1) * HID];   // +1 zero row for CSR padding
__device__ float g_cat[(size_t)N_NODES * CAT_DIM];   // JK concat buffer [N,256]

// ------------------------- helpers --------------------------------------------
__device__ __forceinline__ ull pack2(float a) {
    ull r; asm("mov.b64 %0, {%1, %1};" : "=l"(r) : "f"(a)); return r;
}
__device__ __forceinline__ void ffma2(ull& d, ull a, ull b) {
    asm("fma.rn.f32x2 %0, %1, %2, %0;" : "+l"(d) : "l"(a), "l"(b));
}
__device__ __forceinline__ float lo32(ull v) { return __uint_as_float((unsigned)v); }
__device__ __forceinline__ float hi32(ull v) { return __uint_as_float((unsigned)(v >> 32)); }

// ------------------------- CSR build ------------------------------------------
__global__ void k_zero_deg() {
    int i = blockIdx.x * blockDim.x + threadIdx.x;
    if (i < N_NODES) { g_cnt_in_i[i] = 0; g_cnt_out_i[i] = 0; }
}

// prefill CSR with the zero-row index and zero the pad row of g_y
__global__ void k_prefill() {
    int i = blockIdx.x * blockDim.x + threadIdx.x;
    int4* p = (int4*)g_csr_src;
    if (i < CSR_MAX / 4)
        p[i] = make_int4(N_NODES, N_NODES, N_NODES, N_NODES);
    if (i < HID / 4)
        *(float4*)(g_y + (size_t)N_NODES * HID + i * 4) = make_float4(0.f, 0.f, 0.f, 0.f);
}

__global__ void k_deg_count(const int* __restrict__ src, const int* __restrict__ dst) {
    int e = blockIdx.x * blockDim.x + threadIdx.x;
    if (e < N_EDGES) {
        atomicAdd(&g_cnt_in_i[dst[e]], 1);
        atomicAdd(&g_cnt_out_i[src[e]], 1);
    }
}

// --- hierarchical scan of padded in-degrees -> row_ptr -------------------------
// Phase 1: per-block inclusive scan; write local-exclusive prefix + block total.
__global__ __launch_bounds__(256) void k_scan1() {
    __shared__ int sh[256];
    int t = threadIdx.x;
    int i = blockIdx.x * 256 + t;
    int c = (i < N_NODES) ? ((g_cnt_in_i[i] + 7) & ~7) : 0;
    sh[t] = c;
    __syncthreads();
    #pragma unroll
    for (int off = 1; off < 256; off <<= 1) {
        int a = (t >= off) ? sh[t - off] : 0;
        __syncthreads();
        sh[t] += a;
        __syncthreads();
    }
    if (t == 255) g_blk_sums[blockIdx.x] = sh[255];
    if (i < N_NODES) g_row_ptr[i] = sh[t] - c;   // exclusive within block
}

// Phase 2: single block scans the block sums (exclusive) and writes total.
__global__ __launch_bounds__(256) void k_scan2() {
    __shared__ int sh[256];
    int t = threadIdx.x;
    int v = (t < SCAN_BLOCKS) ? g_blk_sums[t] : 0;
    sh[t] = v;
    __syncthreads();
    #pragma unroll
    for (int off = 1; off < 256; off <<= 1) {
        int a = (t >= off) ? sh[t - off] : 0;
        __syncthreads();
        sh[t] += a;
        __syncthreads();
    }
    if (t < SCAN_BLOCKS) g_blk_off[t] = sh[t] - v;   // exclusive
    if (t == 255) g_row_ptr[N_NODES] = sh[255];      // grand total
}

// Phase 3: add block offsets; finalize cursors and rsqrt normalizers.
__global__ __launch_bounds__(256) void k_scan3() {
    int i = blockIdx.x * 256 + threadIdx.x;
    if (i >= N_NODES) return;
    int rp = g_row_ptr[i] + g_blk_off[blockIdx.x];
    g_row_ptr[i] = rp;
    g_cursor[i]  = rp;
    g_din_is[i]  = rsqrtf((float)max(g_cnt_in_i[i], 1));
    g_dout_is[i] = rsqrtf((float)max(g_cnt_out_i[i], 1));
}

__global__ void k_csr_fill(const int* __restrict__ src, const int* __restrict__ dst) {
    int e = blockIdx.x * blockDim.x + threadIdx.x;
    if (e < N_EDGES) {
        int pos = atomicAdd(&g_cursor[dst[e]], 1);
        g_csr_src[pos] = src[e];
    }
}

// ------------------------- FFMA2 GEMM: Y[n,64] = (diag(s?) X[n,K]) @ W[K,64] ----
template<int K, bool SCALE>
__global__ __launch_bounds__(256)
void k_gemm(const float* __restrict__ X, int ldx,
            const float* __restrict__ W,
            float* __restrict__ Y, int n)
{
    __shared__ float Xs[32][132];
    __shared__ ull   Wd[32][64];

    const int tid  = threadIdx.x;
    const int row0 = blockIdx.x * 128;
    const int r0   = (tid >> 4) * 8;
    const int c0   = (tid & 15) * 4;

    ull acc[4][4];
    #pragma unroll
    for (int p = 0; p < 4; ++p)
        #pragma unroll
        for (int j = 0; j < 4; ++j) acc[p][j] = 0ull;

    for (int kk = 0; kk < K; kk += 32) {
        #pragma unroll
        for (int j = 0; j < 4; ++j) {
            int idx = tid + j * 256;
            int r   = idx >> 3;
            int c4  = (idx & 7) * 4;
            int row = row0 + r;
            float4 v = make_float4(0.f, 0.f, 0.f, 0.f);
            if (row < n) {
                v = *(const float4*)(X + (size_t)row * ldx + kk + c4);
                if (SCALE) {
                    float s = __ldg(&g_dout_is[row]);
                    v.x *= s; v.y *= s; v.z *= s; v.w *= s;
                }
            }
            Xs[c4 + 0][r] = v.x;
            Xs[c4 + 1][r] = v.y;
            Xs[c4 + 2][r] = v.z;
            Xs[c4 + 3][r] = v.w;
        }
        #pragma unroll
        for (int j = 0; j < 8; ++j) {
            int idx = tid + j * 256;
            int k   = idx >> 6;
            int c   = idx & 63;
            Wd[k][c] = pack2(W[(size_t)(kk + k) * 64 + c]);
        }
        __syncthreads();

        #pragma unroll
        for (int k = 0; k < 32; ++k) {
            double2 xa = *(const double2*)&Xs[k][r0];
            double2 xb = *(const double2*)&Xs[k][r0 + 4];
            double2 wA = *(const double2*)&Wd[k][c0];
            double2 wB = *(const double2*)&Wd[k][c0 + 2];
            ull a0 = __double_as_longlong(xa.x);
            ull a1 = __double_as_longlong(xa.y);
            ull a2 = __double_as_longlong(xb.x);
            ull a3 = __double_as_longlong(xb.y);
            ull w0 = __double_as_longlong(wA.x);
            ull w1 = __double_as_longlong(wA.y);
            ull w2 = __double_as_longlong(wB.x);
            ull w3 = __double_as_longlong(wB.y);
            ffma2(acc[0][0], a0, w0); ffma2(acc[0][1], a0, w1); ffma2(acc[0][2], a0, w2); ffma2(acc[0][3], a0, w3);
            ffma2(acc[1][0], a1, w0); ffma2(acc[1][1], a1, w1); ffma2(acc[1][2], a1, w2); ffma2(acc[1][3], a1, w3);
            ffma2(acc[2][0], a2, w0); ffma2(acc[2][1], a2, w1); ffma2(acc[2][2], a2, w2); ffma2(acc[2][3], a2, w3);
            ffma2(acc[3][0], a3, w0); ffma2(acc[3][1], a3, w1); ffma2(acc[3][2], a3, w2); ffma2(acc[3][3], a3, w3);
        }
        __syncthreads();
    }

    #pragma unroll
    for (int p = 0; p < 4; ++p) {
        int rowA = row0 + r0 + 2 * p;
        if (rowA < n) {
            float4 o = make_float4(lo32(acc[p][0]), lo32(acc[p][1]), lo32(acc[p][2]), lo32(acc[p][3]));
            *(float4*)(Y + (size_t)rowA * 64 + c0) = o;
        }
        if (rowA + 1 < n) {
            float4 o = make_float4(hi32(acc[p][0]), hi32(acc[p][1]), hi32(acc[p][2]), hi32(acc[p][3]));
            *(float4*)(Y + (size_t)(rowA + 1) * 64 + c0) = o;
        }
    }
}

// ------------------------- pull aggregation (MLP=8) -----------------------------
template<bool RELU>
__global__ __launch_bounds__(256)
void k_pull(const float* __restrict__ bias, float* __restrict__ outp, int ldo)
{
    int t = blockIdx.x * blockDim.x + threadIdx.x;
    int node = t >> 4;
    if (node >= N_NODES) return;
    int lane4 = (t & 15) << 2;

    int beg = __ldg(&g_row_ptr[node]);
    int end = __ldg(&g_row_ptr[node + 1]);

    float4 accA = make_float4(0.f, 0.f, 0.f, 0.f);
    float4 accB = make_float4(0.f, 0.f, 0.f, 0.f);

    for (int i = beg; i < end; i += 8) {
        int4 sA = __ldg((const int4*)&g_csr_src[i]);
        int4 sB = __ldg((const int4*)&g_csr_src[i + 4]);
        const float* base = g_y + lane4;
        float4 v0 = *(const float4*)(base + (size_t)sA.x * HID);
        float4 v1 = *(const float4*)(base + (size_t)sA.y * HID);
        float4 v2 = *(const float4*)(base + (size_t)sA.z * HID);
        float4 v3 = *(const float4*)(base + (size_t)sA.w * HID);
        float4 v4 = *(const float4*)(base + (size_t)sB.x * HID);
        float4 v5 = *(const float4*)(base + (size_t)sB.y * HID);
        float4 v6 = *(const float4*)(base + (size_t)sB.z * HID);
        float4 v7 = *(const float4*)(base + (size_t)sB.w * HID);
        accA.x += (v0.x + v1.x) + (v2.x + v3.x);
        accA.y += (v0.y + v1.y) + (v2.y + v3.y);
        accA.z += (v0.z + v1.z) + (v2.z + v3.z);
        accA.w += (v0.w + v1.w) + (v2.w + v3.w);
        accB.x += (v4.x + v5.x) + (v6.x + v7.x);
        accB.y += (v4.y + v5.y) + (v6.y + v7.y);
        accB.z += (v4.z + v5.z) + (v6.z + v7.z);
        accB.w += (v4.w + v5.w) + (v6.w + v7.w);
    }

    float4 acc = make_float4(accA.x + accB.x, accA.y + accB.y,
                             accA.z + accB.z, accA.w + accB.w);
    float4 bv = *(const float4*)(bias + lane4);
    float4 o;
    if (RELU) {
        float sc = __ldg(&g_din_is[node]);
        o.x = fmaxf(fmaf(acc.x, sc, bv.x), 0.f);
        o.y = fmaxf(fmaf(acc.y, sc, bv.y), 0.f);
        o.z = fmaxf(fmaf(acc.z, sc, bv.z), 0.f);
        o.w = fmaxf(fmaf(acc.w, sc, bv.w), 0.f);
    } else {
        o.x = acc.x + bv.x; o.y = acc.y + bv.y;
        o.z = acc.z + bv.z; o.w = acc.w + bv.w;
    }
    *(float4*)(outp + (size_t)node * ldo + lane4) = o;
}

// ------------------------- launch ----------------------------------------------
extern "C" void kernel_launch(void* const* d_in, const int* in_sizes, int n_in,
                              void* d_out, int out_size)
{
    const float* feat  = (const float*)d_in[0];
    const int*   src   = (const int*)d_in[1];
    const int*   dst   = (const int*)d_in[2];
    const float* W[4]  = { (const float*)d_in[3], (const float*)d_in[5],
                           (const float*)d_in[7], (const float*)d_in[9] };
    const float* B[4]  = { (const float*)d_in[4], (const float*)d_in[6],
                           (const float*)d_in[8], (const float*)d_in[10] };
    const float* W_mlp = (const float*)d_in[11];
    const float* b_mlp = (const float*)d_in[12];
    float* out = (float*)d_out;

    float *cat_p = nullptr, *y_p = nullptr;
    cudaGetSymbolAddress((void**)&cat_p, g_cat);
    cudaGetSymbolAddress((void**)&y_p, g_y);

    const int T = 256;
    const int gN    = (N_NODES + T - 1) / T;
    const int gE    = (N_EDGES + T - 1) / T;
    const int gPre  = (CSR_MAX / 4 + T - 1) / T;
    const int gPull = (N_NODES * 16 + T - 1) / T;
    const int gGemm = (N_NODES + 127) / 128;

    // CSR build + degree normalizers (hierarchical scan)
    k_zero_deg<<<gN, T>>>();
    k_prefill<<<gPre, T>>>();
    k_deg_count<<<gE, T>>>(src, dst);
    k_scan1<<<SCAN_BLOCKS, 256>>>();
    k_scan2<<<1, 256>>>();
    k_scan3<<<SCAN_BLOCKS, 256>>>();
    k_csr_fill<<<gE, T>>>(src, dst);

    // layer 0: K = 256, input = feat
    k_gemm<256, true><<<gGemm, T>>>(feat, 256, W[0], y_p, N_NODES);
    k_pull<true><<<gPull, T>>>(B[0], cat_p + 0 * HID, CAT_DIM);

    // layers 1..3: K = 64, input = cat column block of previous layer
    for (int l = 1; l < 4; ++l) {
        k_gemm<64, true><<<gGemm, T>>>(cat_p + (l - 1) * HID, CAT_DIM, W[l], y_p, N_NODES);
        k_pull<true><<<gPull, T>>>(B[l], cat_p + l * HID, CAT_DIM);
    }

    // final: out = segment_sum((cat @ W_mlp)[src]) + b  (linearity reorder)
    k_gemm<256, false><<<gGemm, T>>>(cat_p, CAT_DIM, W_mlp, y_p, N_NODES);
    k_pull<false><<<gPull, T>>>(b_mlp, out, HID);
}